// round 4
// baseline (speedup 1.0000x reference)
#include <cuda_runtime.h>
#include <cstdint>

// Problem constants
#define En 64
#define An 8
#define Ln 2048
#define Dn 128
#define Hn 8
#define DKn 16
#define EA 512
#define TL 64
#define STR 132            // padded smem row stride (floats)

typedef unsigned long long ull;

__device__ __forceinline__ ull fma2(ull a, ull b, ull c) {
    ull d; asm("fma.rn.f32x2 %0, %1, %2, %3;" : "=l"(d) : "l"(a), "l"(b), "l"(c)); return d;
}
__device__ __forceinline__ ull mul2(ull a, ull b) {
    ull d; asm("mul.rn.f32x2 %0, %1, %2;" : "=l"(d) : "l"(a), "l"(b)); return d;
}
__device__ __forceinline__ ull pack2(float x, float y) {
    ull r; asm("mov.b64 %0, {%1,%2};" : "=l"(r) : "f"(x), "f"(y)); return r;
}
__device__ __forceinline__ float2 unpack2(ull v) {
    float2 r; asm("mov.b64 {%0,%1}, %2;" : "=f"(r.x), "=f"(r.y) : "l"(v)); return r;
}

// Scratch (device globals: no allocation allowed)
__device__ float g_Gk[Hn * 129 * DKn];       // (Wk_proj @ Wk[h])  [h][129][16]
__device__ float g_Gv[Hn * 129 * DKn];       // (Wv_proj @ Wv[h])  [h][129][16]
__device__ float g_Rk[EA * Hn * Dn];         // per (e,a,h) score vector (scale folded)

// ---------------------------------------------------------------------------
// Kernel 1: fold projection + per-head matrices:  G[h][i][k] = sum_d Wp[i,d]*W[h,d,k]
// ---------------------------------------------------------------------------
__global__ void prep_G(const float* __restrict__ Wk_proj, const float* __restrict__ Wv_proj,
                       const float* __restrict__ Wk, const float* __restrict__ Wv) {
    int idx = blockIdx.x * 256 + threadIdx.x;
    const int TOT = Hn * 129 * DKn;  // 16512
    if (idx >= 2 * TOT) return;
    int which = idx / TOT;
    int r = idx % TOT;
    int h = r / (129 * DKn);
    int r2 = r % (129 * DKn);
    int i = r2 / DKn, k = r2 % DKn;
    const float* Wp = which ? Wv_proj : Wk_proj;
    const float* W  = which ? Wv : Wk;
    float acc = 0.f;
#pragma unroll 8
    for (int d = 0; d < Dn; d++) acc += Wp[i * Dn + d] * W[(h * Dn + d) * DKn + k];
    (which ? g_Gv : g_Gk)[r] = acc;
}

// ---------------------------------------------------------------------------
// Kernel 2: per-(e,a) query pipeline -> Rk[e,a,h][0..127]
//   q = [gc,depot,tbd,load,a] @ Wq_proj ; qh = q @ Wq[h]
//   Rk[h][i] = (0.25*log2e) * sum_k qh[h,k] * Gk[h][i][k]
//   (agent-id K column only shifts scores uniformly -> dropped)
// ---------------------------------------------------------------------------
__global__ void prep_Rk(const float* __restrict__ gc, const float* __restrict__ depot,
                        const float* __restrict__ tbd, const float* __restrict__ loadv,
                        const float* __restrict__ Wq_proj, const float* __restrict__ Wq) {
    __shared__ float qsm[Dn];
    __shared__ float qhsm[Hn * DKn];
    int b = blockIdx.x;
    int e = b >> 3, a = b & 7;
    int t = threadIdx.x;  // 128 threads

    float acc = 0.f;
#pragma unroll 4
    for (int i = 0; i < Dn; i++) acc += gc[e * Dn + i]    * Wq_proj[i * Dn + t];
#pragma unroll 4
    for (int i = 0; i < Dn; i++) acc += depot[e * Dn + i] * Wq_proj[(Dn + i) * Dn + t];
#pragma unroll 4
    for (int i = 0; i < Dn; i++) acc += tbd[e * Dn + i]   * Wq_proj[(2 * Dn + i) * Dn + t];
    acc += loadv[e * An + a] * Wq_proj[384 * Dn + t];
    acc += (float)a          * Wq_proj[385 * Dn + t];
    qsm[t] = acc;
    __syncthreads();

    int h = t >> 4, k = t & 15;
    float q2 = 0.f;
#pragma unroll 4
    for (int d = 0; d < Dn; d++) q2 += qsm[d] * Wq[(h * Dn + d) * DKn + k];
    qhsm[t] = q2;
    __syncthreads();

    const float SC = 0.25f * 1.4426950408889634f;  // 1/sqrt(DK) * log2(e)
#pragma unroll
    for (int j = 0; j < 8; j++) {
        int idx = t + 128 * j;
        int hh = idx >> 7, i = idx & 127;
        float r = 0.f;
#pragma unroll
        for (int kk = 0; kk < DKn; kk++)
            r += qhsm[hh * DKn + kk] * g_Gk[(hh * 129 + i) * DKn + kk];
        g_Rk[(b * Hn + hh) * Dn + i] = SC * r;
    }
}

// ---------------------------------------------------------------------------
// Kernel 3: main streaming kernel. One CTA per (e,a). 256 threads.
// smem layout (floats):
//   [0 .. 16896)      : two 64x132 tile buffers (double-buffered via cp.async)
//   [16896 .. 17952)  : Rksm [8][132]
//   [17952 .. 18528)  : sS   [64][9] raw scores (log2 domain)
//   [18528 .. 19552)  : sPd  [8][64] float2 (p duplicated into both halves)
//   [19552 .. 19576)  : sM[8], sZ[8], sF[8]
//   [19576 .. 19704)  : sCtx[128]
// Epilogue aliases tile region: Wacc[4][8][128] at 0, wf[8][128] at 4096.
// ---------------------------------------------------------------------------
#define SMEM_FLOATS 19704
#define SMEM_BYTES  (SMEM_FLOATS * 4)

__device__ __forceinline__ void load_tile_async(const float* src, uint32_t dbase, int t) {
#pragma unroll
    for (int j = 0; j < 8; j++) {
        int c = t + 256 * j;          // 2048 16B chunks
        int l = c >> 5, s = c & 31;
        uint32_t dst = dbase + (uint32_t)(l * (STR * 4) + s * 16);
        const float* g = src + l * Dn + s * 4;
        asm volatile("cp.async.cg.shared.global [%0], [%1], 16;\n" :: "r"(dst), "l"(g) : "memory");
    }
    asm volatile("cp.async.commit_group;\n" ::: "memory");
}

__global__ __launch_bounds__(256, 2)
void decoder_main(const float* __restrict__ emb, const int* __restrict__ lens,
                  const float* __restrict__ Wo, float* __restrict__ out) {
    extern __shared__ float sm[];
    float* tile  = sm;                     // [2][64][132]
    float* Rksm  = sm + 16896;             // [8][132]
    float* sS    = sm + 17952;             // [64][9]
    float2* sPd  = (float2*)(sm + 18528);  // [8][64]
    float* sM    = sm + 19552;
    float* sZ    = sm + 19560;
    float* sF    = sm + 19568;
    float* sCtx  = sm + 19576;

    int b = blockIdx.x;
    int e = b >> 3, a = b & 7;
    int t = threadIdx.x;
    int len = lens[e * An + a];
    int ntiles = (len + TL - 1) >> 6;
    const float* embp = emb + (size_t)(e * An + a) * (Ln * Dn);

    // load this pair's Rk into smem with pad-132 rows
    {
        const float* rk = g_Rk + (size_t)b * Hn * Dn;
        for (int j = t; j < Hn * Dn; j += 256) {
            int h = j >> 7, i = j & 127;
            Rksm[h * STR + i] = rk[j];
        }
    }
    if (t < 8) { sM[t] = -1e30f; sZ[t] = 0.f; }

    uint32_t smem_u32 = (uint32_t)__cvta_generic_to_shared(sm);

    // per-thread V accumulators: 8 heads, 1 d-pair each, over this thread's l-stripe
    ull w[Hn];
#pragma unroll
    for (int h = 0; h < Hn; h++) w[h] = 0ull;

    // prologue
    load_tile_async(embp, smem_u32, t);

    for (int tt = 0; tt < ntiles; tt++) {
        int cur = tt & 1;
        if (tt + 1 < ntiles) {
            load_tile_async(embp + (size_t)(tt + 1) * TL * Dn,
                            smem_u32 + (cur ^ 1) * (TL * STR * 4), t);
            asm volatile("cp.async.wait_group 1;\n" ::: "memory");
        } else {
            asm volatile("cp.async.wait_group 0;\n" ::: "memory");
        }
        __syncthreads();

        const float* tb = tile + cur * (TL * STR);

        // ---- score pass: thread (h = t&7, lr = t>>3) does rows lr, lr+32 ----
        {
            int h = t & 7, lr = t >> 3;
            const ull* rkp = (const ull*)(Rksm + h * STR);
            const ull* r0  = (const ull*)(tb + lr * STR);
            const ull* r1  = (const ull*)(tb + (lr + 32) * STR);
            ull acc0 = 0ull, acc1 = 0ull;
#pragma unroll 16
            for (int dp = 0; dp < 64; dp++) {
                ull rk = rkp[dp];
                acc0 = fma2(r0[dp], rk, acc0);
                acc1 = fma2(r1[dp], rk, acc1);
            }
            float2 a0 = unpack2(acc0), a1 = unpack2(acc1);
            float s0 = a0.x + a0.y, s1 = a1.x + a1.y;
            int l0 = tt * TL + lr;
            if (l0 >= len)      s0 = -1e30f;
            if (l0 + 32 >= len) s1 = -1e30f;
            sS[lr * 9 + h]        = s0;
            sS[(lr + 32) * 9 + h] = s1;
        }
        __syncthreads();

        // ---- online softmax update: warp h handles head h ----
        {
            int h = t >> 5, j = t & 31;
            float v0 = sS[j * 9 + h], v1 = sS[(j + 32) * 9 + h];
            float tm = fmaxf(v0, v1);
#pragma unroll
            for (int o = 16; o; o >>= 1) tm = fmaxf(tm, __shfl_xor_sync(0xffffffffu, tm, o));
            float mo = sM[h];
            float mn = fmaxf(mo, tm);
            float p0 = exp2f(v0 - mn);
            float p1 = exp2f(v1 - mn);
            float ps = p0 + p1;
#pragma unroll
            for (int o = 16; o; o >>= 1) ps += __shfl_xor_sync(0xffffffffu, ps, o);
            if (j == 0) {
                float fh = exp2f(mo - mn);
                sF[h] = fh;
                sM[h] = mn;
                sZ[h] = sZ[h] * fh + ps;
            }
            sPd[h * 64 + j]      = make_float2(p0, p0);
            sPd[h * 64 + j + 32] = make_float2(p1, p1);
        }
        __syncthreads();

        // ---- accumulate pass: thread (dp = t&63, g = t>>6) rows l = g + 4i ----
        {
            int dp = t & 63, g = t >> 6;
#pragma unroll
            for (int h = 0; h < Hn; h++) {
                float fh = sF[h];
                w[h] = mul2(w[h], pack2(fh, fh));
            }
            const ull* pd = (const ull*)sPd;
#pragma unroll 4
            for (int i = 0; i < 16; i++) {
                int l = g + 4 * i;
                ull e2 = *(const ull*)(tb + l * STR + 2 * dp);
#pragma unroll
                for (int h = 0; h < Hn; h++)
                    w[h] = fma2(pd[h * 64 + l], e2, w[h]);
            }
        }
        __syncthreads();
    }

    // ---- epilogue: reduce 4 l-stripe partials, normalize, project Gv, Wo ----
    {
        int dp = t & 63, g = t >> 6;
        float2* Wacc = (float2*)sm;  // [4][8][64] float2 (aliases tile region)
#pragma unroll
        for (int h = 0; h < Hn; h++)
            Wacc[(g * Hn + h) * 64 + dp] = unpack2(w[h]);
    }
    __syncthreads();

    float* WaccF = sm;          // 4096 floats: [g][h][d]
    float* wf    = sm + 4096;   // 1024 floats: [h][d]
#pragma unroll
    for (int j = 0; j < 4; j++) {
        int idx = t + 256 * j;  // idx = h*128 + d
        int h = idx >> 7;
        float s = WaccF[idx] + WaccF[1024 + idx] + WaccF[2048 + idx] + WaccF[3072 + idx];
        wf[idx] = s / sZ[h];
    }
    __syncthreads();

    if (t < 128) {
        int h = t >> 4, k = t & 15;
        const float* gv = g_Gv + (h * 129) * DKn + k;
        const float* wfh = wf + h * Dn;
        float acc = 0.f;
#pragma unroll 4
        for (int i = 0; i < Dn; i++) acc += wfh[i] * gv[i * DKn];
        acc += (float)a * gv[128 * DKn];  // agent-id value bias (sum attn == 1)
        sCtx[t] = acc;
    }
    __syncthreads();

    if (t < 128) {
        float acc = 0.f;
#pragma unroll 4
        for (int j = 0; j < Hn * DKn; j++) acc += sCtx[j] * Wo[j * Dn + t];
        out[(size_t)(e * An + a) * Dn + t] = acc;
    }
}

// ---------------------------------------------------------------------------
extern "C" void kernel_launch(void* const* d_in, const int* in_sizes, int n_in,
                              void* d_out, int out_size) {
    const float* gc      = (const float*)d_in[0];
    const float* depot   = (const float*)d_in[1];
    const float* tbd     = (const float*)d_in[2];
    const float* loadv   = (const float*)d_in[3];
    const float* emb     = (const float*)d_in[4];
    const int*   lens    = (const int*)  d_in[5];
    const float* Wq_proj = (const float*)d_in[6];
    const float* Wk_proj = (const float*)d_in[7];
    const float* Wv_proj = (const float*)d_in[8];
    const float* Wq      = (const float*)d_in[9];
    const float* Wk      = (const float*)d_in[10];
    const float* Wv      = (const float*)d_in[11];
    const float* Wo      = (const float*)d_in[12];
    float* out = (float*)d_out;

    prep_G<<<(2 * Hn * 129 * DKn + 255) / 256, 256>>>(Wk_proj, Wv_proj, Wk, Wv);
    prep_Rk<<<EA, 128>>>(gc, depot, tbd, loadv, Wq_proj, Wq);

    cudaFuncSetAttribute(decoder_main, cudaFuncAttributeMaxDynamicSharedMemorySize, SMEM_BYTES);
    decoder_main<<<EA, 256, SMEM_BYTES>>>(emb, lens, Wo, out);
}

// round 5
// speedup vs baseline: 1.0024x; 1.0024x over previous
#include <cuda_runtime.h>
#include <cstdint>

// Problem constants
#define En 64
#define An 8
#define Ln 2048
#define Dn 128
#define Hn 8
#define DKn 16
#define EA 512
#define TL 64
#define STR 132            // padded smem row stride (floats)

typedef unsigned long long ull;

__device__ __forceinline__ ull fma2(ull a, ull b, ull c) {
    ull d; asm("fma.rn.f32x2 %0, %1, %2, %3;" : "=l"(d) : "l"(a), "l"(b), "l"(c)); return d;
}
__device__ __forceinline__ ull mul2(ull a, ull b) {
    ull d; asm("mul.rn.f32x2 %0, %1, %2;" : "=l"(d) : "l"(a), "l"(b)); return d;
}
__device__ __forceinline__ ull pack2(float x, float y) {
    ull r; asm("mov.b64 %0, {%1,%2};" : "=l"(r) : "f"(x), "f"(y)); return r;
}
__device__ __forceinline__ float2 unpack2(ull v) {
    float2 r; asm("mov.b64 {%0,%1}, %2;" : "=f"(r.x), "=f"(r.y) : "l"(v)); return r;
}

// Scratch (device globals: no allocation allowed)
__device__ float g_Gk[Hn * 129 * DKn];       // (Wk_proj @ Wk[h])  [h][129][16]
__device__ float g_Gv[Hn * 129 * DKn];       // (Wv_proj @ Wv[h])  [h][129][16]
__device__ float g_Rk[EA * Hn * Dn];         // per (e,a,h) score vector (scale folded)

// ---------------------------------------------------------------------------
// Kernel 1: fold projection + per-head matrices:  G[h][i][k] = sum_d Wp[i,d]*W[h,d,k]
// ---------------------------------------------------------------------------
__global__ void prep_G(const float* __restrict__ Wk_proj, const float* __restrict__ Wv_proj,
                       const float* __restrict__ Wk, const float* __restrict__ Wv) {
    int idx = blockIdx.x * 256 + threadIdx.x;
    const int TOT = Hn * 129 * DKn;  // 16512
    if (idx >= 2 * TOT) return;
    int which = idx / TOT;
    int r = idx % TOT;
    int h = r / (129 * DKn);
    int r2 = r % (129 * DKn);
    int i = r2 / DKn, k = r2 % DKn;
    const float* Wp = which ? Wv_proj : Wk_proj;
    const float* W  = which ? Wv : Wk;
    float acc = 0.f;
#pragma unroll 8
    for (int d = 0; d < Dn; d++) acc += Wp[i * Dn + d] * W[(h * Dn + d) * DKn + k];
    (which ? g_Gv : g_Gk)[r] = acc;
}

// ---------------------------------------------------------------------------
// Kernel 2: per-(e,a) query pipeline -> Rk[e,a,h][0..127]
//   q = [gc,depot,tbd,load,a] @ Wq_proj ; qh = q @ Wq[h]
//   Rk[h][i] = (0.25*log2e) * sum_k qh[h,k] * Gk[h][i][k]
//   (agent-id K column only shifts scores uniformly -> dropped)
// ---------------------------------------------------------------------------
__global__ void prep_Rk(const float* __restrict__ gc, const float* __restrict__ depot,
                        const float* __restrict__ tbd, const float* __restrict__ loadv,
                        const float* __restrict__ Wq_proj, const float* __restrict__ Wq) {
    __shared__ float qsm[Dn];
    __shared__ float qhsm[Hn * DKn];
    int b = blockIdx.x;
    int e = b >> 3, a = b & 7;
    int t = threadIdx.x;  // 128 threads

    float acc = 0.f;
#pragma unroll 4
    for (int i = 0; i < Dn; i++) acc += gc[e * Dn + i]    * Wq_proj[i * Dn + t];
#pragma unroll 4
    for (int i = 0; i < Dn; i++) acc += depot[e * Dn + i] * Wq_proj[(Dn + i) * Dn + t];
#pragma unroll 4
    for (int i = 0; i < Dn; i++) acc += tbd[e * Dn + i]   * Wq_proj[(2 * Dn + i) * Dn + t];
    acc += loadv[e * An + a] * Wq_proj[384 * Dn + t];
    acc += (float)a          * Wq_proj[385 * Dn + t];
    qsm[t] = acc;
    __syncthreads();

    int h = t >> 4, k = t & 15;
    float q2 = 0.f;
#pragma unroll 4
    for (int d = 0; d < Dn; d++) q2 += qsm[d] * Wq[(h * Dn + d) * DKn + k];
    qhsm[t] = q2;
    __syncthreads();

    const float SC = 0.25f * 1.4426950408889634f;  // 1/sqrt(DK) * log2(e)
#pragma unroll
    for (int j = 0; j < 8; j++) {
        int idx = t + 128 * j;
        int hh = idx >> 7, i = idx & 127;
        float r = 0.f;
#pragma unroll
        for (int kk = 0; kk < DKn; kk++)
            r += qhsm[hh * DKn + kk] * g_Gk[(hh * 129 + i) * DKn + kk];
        g_Rk[(b * Hn + hh) * Dn + i] = SC * r;
    }
}

// ---------------------------------------------------------------------------
// Kernel 3: main streaming kernel. One CTA per (e,a). 256 threads.
// smem layout (floats):
//   [0 .. 16896)      : two 64x132 tile buffers (double-buffered via cp.async)
//   [16896 .. 17952)  : Rksm [8][132]
//   [17952 .. 18528)  : sS   [64][9] raw scores (log2 domain)
//   [18528 .. 19552)  : sPd  [8][64] float2 (p duplicated into both halves)
//   [19552 .. 19576)  : sM[8], sZ[8], sF[8]
//   [19576 .. 19704)  : sCtx[128]
// Epilogue aliases tile region: Wacc[4][8][128] at 0, wf[8][128] at 4096.
// ---------------------------------------------------------------------------
#define SMEM_FLOATS 19704
#define SMEM_BYTES  (SMEM_FLOATS * 4)

__device__ __forceinline__ void load_tile_async(const float* src, uint32_t dbase, int t) {
#pragma unroll
    for (int j = 0; j < 8; j++) {
        int c = t + 256 * j;          // 2048 16B chunks
        int l = c >> 5, s = c & 31;
        uint32_t dst = dbase + (uint32_t)(l * (STR * 4) + s * 16);
        const float* g = src + l * Dn + s * 4;
        asm volatile("cp.async.cg.shared.global [%0], [%1], 16;\n" :: "r"(dst), "l"(g) : "memory");
    }
    asm volatile("cp.async.commit_group;\n" ::: "memory");
}

__global__ __launch_bounds__(256, 2)
void decoder_main(const float* __restrict__ emb, const int* __restrict__ lens,
                  const float* __restrict__ Wo, float* __restrict__ out) {
    extern __shared__ float sm[];
    float* tile  = sm;                     // [2][64][132]
    float* Rksm  = sm + 16896;             // [8][132]
    float* sS    = sm + 17952;             // [64][9]
    float2* sPd  = (float2*)(sm + 18528);  // [8][64]
    float* sM    = sm + 19552;
    float* sZ    = sm + 19560;
    float* sF    = sm + 19568;
    float* sCtx  = sm + 19576;

    int b = blockIdx.x;
    int e = b >> 3, a = b & 7;
    int t = threadIdx.x;
    int len = lens[e * An + a];
    int ntiles = (len + TL - 1) >> 6;
    const float* embp = emb + (size_t)(e * An + a) * (Ln * Dn);

    // load this pair's Rk into smem with pad-132 rows
    {
        const float* rk = g_Rk + (size_t)b * Hn * Dn;
        for (int j = t; j < Hn * Dn; j += 256) {
            int h = j >> 7, i = j & 127;
            Rksm[h * STR + i] = rk[j];
        }
    }
    if (t < 8) { sM[t] = -1e30f; sZ[t] = 0.f; }

    uint32_t smem_u32 = (uint32_t)__cvta_generic_to_shared(sm);

    // per-thread V accumulators: 8 heads, 1 d-pair each, over this thread's l-stripe
    ull w[Hn];
#pragma unroll
    for (int h = 0; h < Hn; h++) w[h] = 0ull;

    // prologue
    load_tile_async(embp, smem_u32, t);

    for (int tt = 0; tt < ntiles; tt++) {
        int cur = tt & 1;
        if (tt + 1 < ntiles) {
            load_tile_async(embp + (size_t)(tt + 1) * TL * Dn,
                            smem_u32 + (cur ^ 1) * (TL * STR * 4), t);
            asm volatile("cp.async.wait_group 1;\n" ::: "memory");
        } else {
            asm volatile("cp.async.wait_group 0;\n" ::: "memory");
        }
        __syncthreads();

        const float* tb = tile + cur * (TL * STR);

        // ---- score pass: thread (h = t&7, lr = t>>3) does rows lr, lr+32 ----
        {
            int h = t & 7, lr = t >> 3;
            const ull* rkp = (const ull*)(Rksm + h * STR);
            const ull* r0  = (const ull*)(tb + lr * STR);
            const ull* r1  = (const ull*)(tb + (lr + 32) * STR);
            ull acc0 = 0ull, acc1 = 0ull;
#pragma unroll 16
            for (int dp = 0; dp < 64; dp++) {
                ull rk = rkp[dp];
                acc0 = fma2(r0[dp], rk, acc0);
                acc1 = fma2(r1[dp], rk, acc1);
            }
            float2 a0 = unpack2(acc0), a1 = unpack2(acc1);
            float s0 = a0.x + a0.y, s1 = a1.x + a1.y;
            int l0 = tt * TL + lr;
            if (l0 >= len)      s0 = -1e30f;
            if (l0 + 32 >= len) s1 = -1e30f;
            sS[lr * 9 + h]        = s0;
            sS[(lr + 32) * 9 + h] = s1;
        }
        __syncthreads();

        // ---- online softmax update: warp h handles head h ----
        {
            int h = t >> 5, j = t & 31;
            float v0 = sS[j * 9 + h], v1 = sS[(j + 32) * 9 + h];
            float tm = fmaxf(v0, v1);
#pragma unroll
            for (int o = 16; o; o >>= 1) tm = fmaxf(tm, __shfl_xor_sync(0xffffffffu, tm, o));
            float mo = sM[h];
            float mn = fmaxf(mo, tm);
            float p0 = exp2f(v0 - mn);
            float p1 = exp2f(v1 - mn);
            float ps = p0 + p1;
#pragma unroll
            for (int o = 16; o; o >>= 1) ps += __shfl_xor_sync(0xffffffffu, ps, o);
            if (j == 0) {
                float fh = exp2f(mo - mn);
                sF[h] = fh;
                sM[h] = mn;
                sZ[h] = sZ[h] * fh + ps;
            }
            sPd[h * 64 + j]      = make_float2(p0, p0);
            sPd[h * 64 + j + 32] = make_float2(p1, p1);
        }
        __syncthreads();

        // ---- accumulate pass: thread (dp = t&63, g = t>>6) rows l = g + 4i ----
        {
            int dp = t & 63, g = t >> 6;
#pragma unroll
            for (int h = 0; h < Hn; h++) {
                float fh = sF[h];
                w[h] = mul2(w[h], pack2(fh, fh));
            }
            const ull* pd = (const ull*)sPd;
#pragma unroll 4
            for (int i = 0; i < 16; i++) {
                int l = g + 4 * i;
                ull e2 = *(const ull*)(tb + l * STR + 2 * dp);
#pragma unroll
                for (int h = 0; h < Hn; h++)
                    w[h] = fma2(pd[h * 64 + l], e2, w[h]);
            }
        }
        __syncthreads();
    }

    // ---- epilogue: reduce 4 l-stripe partials, normalize, project Gv, Wo ----
    {
        int dp = t & 63, g = t >> 6;
        float2* Wacc = (float2*)sm;  // [4][8][64] float2 (aliases tile region)
#pragma unroll
        for (int h = 0; h < Hn; h++)
            Wacc[(g * Hn + h) * 64 + dp] = unpack2(w[h]);
    }
    __syncthreads();

    float* WaccF = sm;          // 4096 floats: [g][h][d]
    float* wf    = sm + 4096;   // 1024 floats: [h][d]
#pragma unroll
    for (int j = 0; j < 4; j++) {
        int idx = t + 256 * j;  // idx = h*128 + d
        int h = idx >> 7;
        float s = WaccF[idx] + WaccF[1024 + idx] + WaccF[2048 + idx] + WaccF[3072 + idx];
        wf[idx] = s / sZ[h];
    }
    __syncthreads();

    if (t < 128) {
        int h = t >> 4, k = t & 15;
        const float* gv = g_Gv + (h * 129) * DKn + k;
        const float* wfh = wf + h * Dn;
        float acc = 0.f;
#pragma unroll 4
        for (int i = 0; i < Dn; i++) acc += wfh[i] * gv[i * DKn];
        acc += (float)a * gv[128 * DKn];  // agent-id value bias (sum attn == 1)
        sCtx[t] = acc;
    }
    __syncthreads();

    if (t < 128) {
        float acc = 0.f;
#pragma unroll 4
        for (int j = 0; j < Hn * DKn; j++) acc += sCtx[j] * Wo[j * Dn + t];
        out[(size_t)(e * An + a) * Dn + t] = acc;
    }
}

// ---------------------------------------------------------------------------
extern "C" void kernel_launch(void* const* d_in, const int* in_sizes, int n_in,
                              void* d_out, int out_size) {
    const float* gc      = (const float*)d_in[0];
    const float* depot   = (const float*)d_in[1];
    const float* tbd     = (const float*)d_in[2];
    const float* loadv   = (const float*)d_in[3];
    const float* emb     = (const float*)d_in[4];
    const int*   lens    = (const int*)  d_in[5];
    const float* Wq_proj = (const float*)d_in[6];
    const float* Wk_proj = (const float*)d_in[7];
    const float* Wv_proj = (const float*)d_in[8];
    const float* Wq      = (const float*)d_in[9];
    const float* Wk      = (const float*)d_in[10];
    const float* Wv      = (const float*)d_in[11];
    const float* Wo      = (const float*)d_in[12];
    float* out = (float*)d_out;

    prep_G<<<(2 * Hn * 129 * DKn + 255) / 256, 256>>>(Wk_proj, Wv_proj, Wk, Wv);
    prep_Rk<<<EA, 128>>>(gc, depot, tbd, loadv, Wq_proj, Wq);

    cudaFuncSetAttribute(decoder_main, cudaFuncAttributeMaxDynamicSharedMemorySize, SMEM_BYTES);
    decoder_main<<<EA, 256, SMEM_BYTES>>>(emb, lens, Wo, out);
}

// round 6
// speedup vs baseline: 1.0206x; 1.0181x over previous
#include <cuda_runtime.h>
#include <cstdint>

// Problem constants
#define En 64
#define An 8
#define Ln 2048
#define Dn 128
#define Hn 8
#define DKn 16
#define EA 512
#define TL 64
#define STR 132            // padded smem row stride (floats)

typedef unsigned long long ull;

__device__ __forceinline__ ull fma2(ull a, ull b, ull c) {
    ull d; asm("fma.rn.f32x2 %0, %1, %2, %3;" : "=l"(d) : "l"(a), "l"(b), "l"(c)); return d;
}
__device__ __forceinline__ ull mul2(ull a, ull b) {
    ull d; asm("mul.rn.f32x2 %0, %1, %2;" : "=l"(d) : "l"(a), "l"(b)); return d;
}
__device__ __forceinline__ ull pack2(float x, float y) {
    ull r; asm("mov.b64 %0, {%1,%2};" : "=l"(r) : "f"(x), "f"(y)); return r;
}
__device__ __forceinline__ float2 unpack2(ull v) {
    float2 r; asm("mov.b64 {%0,%1}, %2;" : "=f"(r.x), "=f"(r.y) : "l"(v)); return r;
}

// Scratch (device globals: no allocation allowed)
__device__ float g_Gk[Hn * 129 * DKn];       // (Wk_proj @ Wk[h])  [h][129][16]
__device__ float g_Gv[Hn * 129 * DKn];       // (Wv_proj @ Wv[h])  [h][129][16]
__device__ float g_Rk[EA * Hn * Dn];         // per (e,a,h) score vector (scale folded)

// ---------------------------------------------------------------------------
// Kernel 1: fold projection + per-head matrices:  G[h][i][k] = sum_d Wp[i,d]*W[h,d,k]
// ---------------------------------------------------------------------------
__global__ void prep_G(const float* __restrict__ Wk_proj, const float* __restrict__ Wv_proj,
                       const float* __restrict__ Wk, const float* __restrict__ Wv) {
    int idx = blockIdx.x * 256 + threadIdx.x;
    const int TOT = Hn * 129 * DKn;  // 16512
    if (idx >= 2 * TOT) return;
    int which = idx / TOT;
    int r = idx % TOT;
    int h = r / (129 * DKn);
    int r2 = r % (129 * DKn);
    int i = r2 / DKn, k = r2 % DKn;
    const float* Wp = which ? Wv_proj : Wk_proj;
    const float* W  = which ? Wv : Wk;
    float acc = 0.f;
#pragma unroll 8
    for (int d = 0; d < Dn; d++) acc += Wp[i * Dn + d] * W[(h * Dn + d) * DKn + k];
    (which ? g_Gv : g_Gk)[r] = acc;
}

// ---------------------------------------------------------------------------
// Kernel 2: per-(e,a) query pipeline -> Rk[e,a,h][0..127]
//   q = [gc,depot,tbd,load,a] @ Wq_proj ; qh = q @ Wq[h]
//   Rk[h][i] = (0.25*log2e) * sum_k qh[h,k] * Gk[h][i][k]
//   (agent-id K column only shifts scores uniformly -> dropped)
// ---------------------------------------------------------------------------
__global__ void prep_Rk(const float* __restrict__ gc, const float* __restrict__ depot,
                        const float* __restrict__ tbd, const float* __restrict__ loadv,
                        const float* __restrict__ Wq_proj, const float* __restrict__ Wq) {
    __shared__ float qsm[Dn];
    __shared__ float qhsm[Hn * DKn];
    int b = blockIdx.x;
    int e = b >> 3, a = b & 7;
    int t = threadIdx.x;  // 128 threads

    float acc = 0.f;
#pragma unroll 4
    for (int i = 0; i < Dn; i++) acc += gc[e * Dn + i]    * Wq_proj[i * Dn + t];
#pragma unroll 4
    for (int i = 0; i < Dn; i++) acc += depot[e * Dn + i] * Wq_proj[(Dn + i) * Dn + t];
#pragma unroll 4
    for (int i = 0; i < Dn; i++) acc += tbd[e * Dn + i]   * Wq_proj[(2 * Dn + i) * Dn + t];
    acc += loadv[e * An + a] * Wq_proj[384 * Dn + t];
    acc += (float)a          * Wq_proj[385 * Dn + t];
    qsm[t] = acc;
    __syncthreads();

    int h = t >> 4, k = t & 15;
    float q2 = 0.f;
#pragma unroll 4
    for (int d = 0; d < Dn; d++) q2 += qsm[d] * Wq[(h * Dn + d) * DKn + k];
    qhsm[t] = q2;
    __syncthreads();

    const float SC = 0.25f * 1.4426950408889634f;  // 1/sqrt(DK) * log2(e)
#pragma unroll
    for (int j = 0; j < 8; j++) {
        int idx = t + 128 * j;
        int hh = idx >> 7, i = idx & 127;
        float r = 0.f;
#pragma unroll
        for (int kk = 0; kk < DKn; kk++)
            r += qhsm[hh * DKn + kk] * g_Gk[(hh * 129 + i) * DKn + kk];
        g_Rk[(b * Hn + hh) * Dn + i] = SC * r;
    }
}

// ---------------------------------------------------------------------------
// Kernel 3: main streaming kernel. One CTA per (e,a). 256 threads.
// smem layout (floats):
//   [0 .. 16896)      : two 64x132 tile buffers (double-buffered via cp.async)
//   [16896 .. 17952)  : Rksm [8][132]
//   [17952 .. 18528)  : sS   [64][9] raw scores (log2 domain)
//   [18528 .. 19552)  : sPd  [8][64] float2 (p duplicated into both halves)
//   [19552 .. 19576)  : sM[8], sZ[8], sF[8]
//   [19576 .. 19704)  : sCtx[128]
// Epilogue aliases tile region: Wacc[4][8][128] at 0, wf[8][128] at 4096.
// ---------------------------------------------------------------------------
#define SMEM_FLOATS 19704
#define SMEM_BYTES  (SMEM_FLOATS * 4)

__device__ __forceinline__ void load_tile_async(const float* src, uint32_t dbase, int t) {
#pragma unroll
    for (int j = 0; j < 8; j++) {
        int c = t + 256 * j;          // 2048 16B chunks
        int l = c >> 5, s = c & 31;
        uint32_t dst = dbase + (uint32_t)(l * (STR * 4) + s * 16);
        const float* g = src + l * Dn + s * 4;
        asm volatile("cp.async.cg.shared.global [%0], [%1], 16;\n" :: "r"(dst), "l"(g) : "memory");
    }
    asm volatile("cp.async.commit_group;\n" ::: "memory");
}

__global__ __launch_bounds__(256, 2)
void decoder_main(const float* __restrict__ emb, const int* __restrict__ lens,
                  const float* __restrict__ Wo, float* __restrict__ out) {
    extern __shared__ float sm[];
    float* tile  = sm;                     // [2][64][132]
    float* Rksm  = sm + 16896;             // [8][132]
    float* sS    = sm + 17952;             // [64][9]
    float2* sPd  = (float2*)(sm + 18528);  // [8][64]
    float* sM    = sm + 19552;
    float* sZ    = sm + 19560;
    float* sF    = sm + 19568;
    float* sCtx  = sm + 19576;

    int b = blockIdx.x;
    int e = b >> 3, a = b & 7;
    int t = threadIdx.x;
    int len = lens[e * An + a];
    int ntiles = (len + TL - 1) >> 6;
    const float* embp = emb + (size_t)(e * An + a) * (Ln * Dn);

    // load this pair's Rk into smem with pad-132 rows
    {
        const float* rk = g_Rk + (size_t)b * Hn * Dn;
        for (int j = t; j < Hn * Dn; j += 256) {
            int h = j >> 7, i = j & 127;
            Rksm[h * STR + i] = rk[j];
        }
    }
    if (t < 8) { sM[t] = -1e30f; sZ[t] = 0.f; }

    uint32_t smem_u32 = (uint32_t)__cvta_generic_to_shared(sm);

    // per-thread V accumulators: 8 heads, 1 d-pair each, over this thread's l-stripe
    ull w[Hn];
#pragma unroll
    for (int h = 0; h < Hn; h++) w[h] = 0ull;

    // prologue
    load_tile_async(embp, smem_u32, t);

    for (int tt = 0; tt < ntiles; tt++) {
        int cur = tt & 1;
        if (tt + 1 < ntiles) {
            load_tile_async(embp + (size_t)(tt + 1) * TL * Dn,
                            smem_u32 + (cur ^ 1) * (TL * STR * 4), t);
            asm volatile("cp.async.wait_group 1;\n" ::: "memory");
        } else {
            asm volatile("cp.async.wait_group 0;\n" ::: "memory");
        }
        __syncthreads();

        const float* tb = tile + cur * (TL * STR);

        // ---- score pass: thread (h = t&7, lr = t>>3) does rows lr, lr+32 ----
        {
            int h = t & 7, lr = t >> 3;
            const ull* rkp = (const ull*)(Rksm + h * STR);
            const ull* r0  = (const ull*)(tb + lr * STR);
            const ull* r1  = (const ull*)(tb + (lr + 32) * STR);
            ull acc0 = 0ull, acc1 = 0ull;
#pragma unroll 16
            for (int dp = 0; dp < 64; dp++) {
                ull rk = rkp[dp];
                acc0 = fma2(r0[dp], rk, acc0);
                acc1 = fma2(r1[dp], rk, acc1);
            }
            float2 a0 = unpack2(acc0), a1 = unpack2(acc1);
            float s0 = a0.x + a0.y, s1 = a1.x + a1.y;
            int l0 = tt * TL + lr;
            if (l0 >= len)      s0 = -1e30f;
            if (l0 + 32 >= len) s1 = -1e30f;
            sS[lr * 9 + h]        = s0;
            sS[(lr + 32) * 9 + h] = s1;
        }
        __syncthreads();

        // ---- online softmax update: warp h handles head h ----
        {
            int h = t >> 5, j = t & 31;
            float v0 = sS[j * 9 + h], v1 = sS[(j + 32) * 9 + h];
            float tm = fmaxf(v0, v1);
#pragma unroll
            for (int o = 16; o; o >>= 1) tm = fmaxf(tm, __shfl_xor_sync(0xffffffffu, tm, o));
            float mo = sM[h];
            float mn = fmaxf(mo, tm);
            float p0 = exp2f(v0 - mn);
            float p1 = exp2f(v1 - mn);
            float ps = p0 + p1;
#pragma unroll
            for (int o = 16; o; o >>= 1) ps += __shfl_xor_sync(0xffffffffu, ps, o);
            if (j == 0) {
                float fh = exp2f(mo - mn);
                sF[h] = fh;
                sM[h] = mn;
                sZ[h] = sZ[h] * fh + ps;
            }
            sPd[h * 64 + j]      = make_float2(p0, p0);
            sPd[h * 64 + j + 32] = make_float2(p1, p1);
        }
        __syncthreads();

        // ---- accumulate pass: thread (dp = t&63, g = t>>6) rows l = g + 4i ----
        {
            int dp = t & 63, g = t >> 6;
#pragma unroll
            for (int h = 0; h < Hn; h++) {
                float fh = sF[h];
                w[h] = mul2(w[h], pack2(fh, fh));
            }
            const ull* pd = (const ull*)sPd;
#pragma unroll 4
            for (int i = 0; i < 16; i++) {
                int l = g + 4 * i;
                ull e2 = *(const ull*)(tb + l * STR + 2 * dp);
#pragma unroll
                for (int h = 0; h < Hn; h++)
                    w[h] = fma2(pd[h * 64 + l], e2, w[h]);
            }
        }
        __syncthreads();
    }

    // ---- epilogue: reduce 4 l-stripe partials, normalize, project Gv, Wo ----
    {
        int dp = t & 63, g = t >> 6;
        float2* Wacc = (float2*)sm;  // [4][8][64] float2 (aliases tile region)
#pragma unroll
        for (int h = 0; h < Hn; h++)
            Wacc[(g * Hn + h) * 64 + dp] = unpack2(w[h]);
    }
    __syncthreads();

    float* WaccF = sm;          // 4096 floats: [g][h][d]
    float* wf    = sm + 4096;   // 1024 floats: [h][d]
#pragma unroll
    for (int j = 0; j < 4; j++) {
        int idx = t + 256 * j;  // idx = h*128 + d
        int h = idx >> 7;
        float s = WaccF[idx] + WaccF[1024 + idx] + WaccF[2048 + idx] + WaccF[3072 + idx];
        wf[idx] = s / sZ[h];
    }
    __syncthreads();

    if (t < 128) {
        int h = t >> 4, k = t & 15;
        const float* gv = g_Gv + (h * 129) * DKn + k;
        const float* wfh = wf + h * Dn;
        float acc = 0.f;
#pragma unroll 4
        for (int i = 0; i < Dn; i++) acc += wfh[i] * gv[i * DKn];
        acc += (float)a * gv[128 * DKn];  // agent-id value bias (sum attn == 1)
        sCtx[t] = acc;
    }
    __syncthreads();

    if (t < 128) {
        float acc = 0.f;
#pragma unroll 4
        for (int j = 0; j < Hn * DKn; j++) acc += sCtx[j] * Wo[j * Dn + t];
        out[(size_t)(e * An + a) * Dn + t] = acc;
    }
}

// ---------------------------------------------------------------------------
extern "C" void kernel_launch(void* const* d_in, const int* in_sizes, int n_in,
                              void* d_out, int out_size) {
    const float* gc      = (const float*)d_in[0];
    const float* depot   = (const float*)d_in[1];
    const float* tbd     = (const float*)d_in[2];
    const float* loadv   = (const float*)d_in[3];
    const float* emb     = (const float*)d_in[4];
    const int*   lens    = (const int*)  d_in[5];
    const float* Wq_proj = (const float*)d_in[6];
    const float* Wk_proj = (const float*)d_in[7];
    const float* Wv_proj = (const float*)d_in[8];
    const float* Wq      = (const float*)d_in[9];
    const float* Wk      = (const float*)d_in[10];
    const float* Wv      = (const float*)d_in[11];
    const float* Wo      = (const float*)d_in[12];
    float* out = (float*)d_out;

    prep_G<<<(2 * Hn * 129 * DKn + 255) / 256, 256>>>(Wk_proj, Wv_proj, Wk, Wv);
    prep_Rk<<<EA, 128>>>(gc, depot, tbd, loadv, Wq_proj, Wq);

    cudaFuncSetAttribute(decoder_main, cudaFuncAttributeMaxDynamicSharedMemorySize, SMEM_BYTES);
    decoder_main<<<EA, 256, SMEM_BYTES>>>(emb, lens, Wo, out);
}

// round 8
// speedup vs baseline: 1.2399x; 1.2149x over previous
#include <cuda_runtime.h>
#include <cstdint>

#define En 64
#define An 8
#define Ln 2048
#define Dn 128
#define Hn 8
#define DKn 16
#define EA 512
#define SPLIT 4
#define RPS 512
#define TL 64
#define STR 132

typedef unsigned long long ull;

__device__ __forceinline__ ull fma2(ull a, ull b, ull c) {
    ull d; asm("fma.rn.f32x2 %0, %1, %2, %3;" : "=l"(d) : "l"(a), "l"(b), "l"(c)); return d;
}
__device__ __forceinline__ ull mul2(ull a, ull b) {
    ull d; asm("mul.rn.f32x2 %0, %1, %2;" : "=l"(d) : "l"(a), "l"(b)); return d;
}
__device__ __forceinline__ float2 unpack2(ull v) {
    float2 r; asm("mov.b64 {%0,%1}, %2;" : "=f"(r.x), "=f"(r.y) : "l"(v)); return r;
}
__device__ __forceinline__ float ex2(float x) {
    float y; asm("ex2.approx.ftz.f32 %0, %1;" : "=f"(y) : "f"(x)); return y;
}

__device__ __align__(16) float g_bq[3 * En * Dn];
__device__ __align__(16) float g_Rk[EA * Hn * Dn];
__device__ __align__(16) float g_part[EA * SPLIT * 1040];  // m[8],Z[8],w[8][128]

// ---------------- Kernel 1: base query partials ----------------
__global__ void prep_base(const float* __restrict__ gc, const float* __restrict__ dep,
                          const float* __restrict__ tbd, const float* __restrict__ Wqp) {
    int e = blockIdx.x / 3, seg = blockIdx.x % 3, t = threadIdx.x;
    const float* src = ((seg == 0) ? gc : (seg == 1) ? dep : tbd) + e * Dn;
    const float* wp = Wqp + seg * Dn * Dn + t;
    float acc = 0.f;
#pragma unroll 8
    for (int i = 0; i < Dn; i++) acc += src[i] * wp[i * Dn];
    g_bq[(seg * En + e) * Dn + t] = acc;
}

// ---------------- Kernel 2: Rk[b][h][i] (scale+log2e folded; agent-id K col drops) ----------------
__global__ void prep_Rk(const float* __restrict__ loadv, const float* __restrict__ Wqp,
                        const float* __restrict__ Wq, const float* __restrict__ Wk,
                        const float* __restrict__ Wkp) {
    __shared__ float qsm[Dn];
    __shared__ float qhs[Hn * DKn];
    __shared__ float ut[Dn * Hn];
    int b = blockIdx.x, e = b >> 3, a = b & 7, t = threadIdx.x;

    qsm[t] = g_bq[e * Dn + t] + g_bq[(En + e) * Dn + t] + g_bq[(2 * En + e) * Dn + t]
           + loadv[e * An + a] * Wqp[384 * Dn + t] + (float)a * Wqp[385 * Dn + t];
    __syncthreads();
    {
        int h = t >> 4, k = t & 15;
        float acc = 0.f;
#pragma unroll 4
        for (int d = 0; d < Dn; d++) acc += qsm[d] * Wq[(h * Dn + d) * DKn + k];
        qhs[t] = acc;
    }
    __syncthreads();
    {
        const float SC = 0.25f * 1.4426950408889634f;
#pragma unroll
        for (int h = 0; h < Hn; h++) {
            const float* wkr = Wk + (h * Dn + t) * DKn;
            const float* qh = qhs + h * DKn;
            float acc = 0.f;
#pragma unroll
            for (int k = 0; k < DKn; k++) acc += qh[k] * wkr[k];
            ut[t * Hn + h] = SC * acc;
        }
    }
    __syncthreads();
    {
        float acc[Hn];
#pragma unroll
        for (int h = 0; h < Hn; h++) acc[h] = 0.f;
        const float* wr = Wkp + t * Dn;
#pragma unroll 4
        for (int d = 0; d < Dn; d++) {
            float wv = wr[d];
            const float* u = ut + d * Hn;
#pragma unroll
            for (int h = 0; h < Hn; h++) acc[h] += wv * u[h];
        }
#pragma unroll
        for (int h = 0; h < Hn; h++) g_Rk[((size_t)b * Hn + h) * Dn + t] = acc[h];
    }
}

// ---------------- Kernel 3: main. CTA per (e,a,split). 256 thr ----------------
#define SM_SS 16896
#define SM_SP 17472
#define SM_M  18752
#define SM_Z  18760
#define SM_F  18768
#define SMEM_BYTES (18784 * 4)

__device__ __forceinline__ void load_tile_async(const float* src, uint32_t dbase, int t) {
#pragma unroll
    for (int j = 0; j < 8; j++) {
        int c = t + 256 * j, l = c >> 5, s = c & 31;
        uint32_t dst = dbase + (uint32_t)(l * (STR * 4) + s * 16);
        asm volatile("cp.async.cg.shared.global [%0], [%1], 16;\n"
                     :: "r"(dst), "l"(src + l * Dn + s * 4) : "memory");
    }
    asm volatile("cp.async.commit_group;\n" ::: "memory");
}

__global__ __launch_bounds__(256, 2)
void decoder_main(const float* __restrict__ emb, const int* __restrict__ lens) {
    extern __shared__ float sm[];
    float*  sS  = sm + SM_SS;
    float*  sP  = sm + SM_SP;
    float*  sM  = sm + SM_M;
    float*  sZ  = sm + SM_Z;
    float2* sF2 = (float2*)(sm + SM_F);

    int blk = blockIdx.x, b = blk >> 2, sp = blk & 3, t = threadIdx.x;
    int len = lens[b];
    int cnt = min(len - sp * RPS, RPS);
    int ntiles = (cnt > 0) ? ((cnt + TL - 1) >> 6) : 0;
    const float* embp = emb + (size_t)b * (Ln * Dn) + (size_t)sp * RPS * Dn;

    int h = t & 7, q = (t >> 3) & 3, wrp = t >> 5;

    ull rk[16];
    {
        const float* rbase = g_Rk + ((size_t)b * Hn + h) * Dn + 4 * q;
#pragma unroll
        for (int j = 0; j < 8; j++) {
            ulonglong2 v = *(const ulonglong2*)(rbase + 16 * j);
            rk[2 * j] = v.x; rk[2 * j + 1] = v.y;
        }
    }
    if (t < 8) { sM[t] = -1e30f; sZ[t] = 0.f; }

    ull w0[Hn], w1[Hn];
#pragma unroll
    for (int i = 0; i < Hn; i++) { w0[i] = 0ull; w1[i] = 0ull; }

    uint32_t smb = (uint32_t)__cvta_generic_to_shared(sm);

    if (ntiles > 0) {
        load_tile_async(embp, smb, t);
        if (ntiles > 1) load_tile_async(embp + TL * Dn, smb + TL * STR * 4, t);

        for (int tt = 0; tt < ntiles; tt++) {
            int cur = tt & 1;
            if (tt + 1 < ntiles) asm volatile("cp.async.wait_group 1;\n" ::: "memory");
            else                 asm volatile("cp.async.wait_group 0;\n" ::: "memory");
            __syncthreads();
            const float* tb = sm + cur * (TL * STR);

            // score: warp wrp -> rows wrp*8..+7; lane (h,q)
#pragma unroll
            for (int i = 0; i < 8; i++) {
                int row = wrp * 8 + i;
                const ulonglong2* rp = (const ulonglong2*)(tb + row * STR + 4 * q);
                ull a0 = 0ull, a1 = 0ull;
#pragma unroll
                for (int j = 0; j < 8; j++) {
                    ulonglong2 ev = rp[4 * j];
                    a0 = fma2(ev.x, rk[2 * j], a0);
                    a1 = fma2(ev.y, rk[2 * j + 1], a1);
                }
                float2 fa = unpack2(a0), fb = unpack2(a1);
                float s = (fa.x + fa.y) + (fb.x + fb.y);
                s += __shfl_xor_sync(0xffffffffu, s, 8);
                s += __shfl_xor_sync(0xffffffffu, s, 16);
                if (tt * TL + row >= cnt) s = -1e30f;
                if (q == 0) sS[row * 9 + h] = s;
            }
            __syncthreads();

            // online softmax: warp wrp = head
            {
                int j = t & 31;
                float v0 = sS[j * 9 + wrp], v1 = sS[(j + 32) * 9 + wrp];
                float tm = fmaxf(v0, v1);
#pragma unroll
                for (int o = 16; o; o >>= 1) tm = fmaxf(tm, __shfl_xor_sync(0xffffffffu, tm, o));
                float mo = sM[wrp], mn = fmaxf(mo, tm);
                float p0 = ex2(v0 - mn), p1 = ex2(v1 - mn);
                float ps = p0 + p1;
#pragma unroll
                for (int o = 16; o; o >>= 1) ps += __shfl_xor_sync(0xffffffffu, ps, o);
                if (j == 0) {
                    float fh = ex2(mo - mn);
                    sF2[wrp] = make_float2(fh, fh);
                    sM[wrp] = mn;
                    sZ[wrp] = sZ[wrp] * fh + ps;
                }
                *(float2*)(sP + j * 20 + 2 * wrp)        = make_float2(p0, p0);
                *(float2*)(sP + (j + 32) * 20 + 2 * wrp) = make_float2(p1, p1);
            }
            __syncthreads();

            // accumulate: warp wrp -> rows wrp*8..+7; lane dq -> floats 4dq..+3
            {
                int dq = t & 31;
#pragma unroll
                for (int i = 0; i < Hn; i++) {
                    ull f2v = ((const ull*)sF2)[i];
                    w0[i] = mul2(w0[i], f2v);
                    w1[i] = mul2(w1[i], f2v);
                }
#pragma unroll
                for (int i = 0; i < 8; i++) {
                    int l = wrp * 8 + i;
                    ulonglong2 ev = *(const ulonglong2*)(tb + l * STR + 4 * dq);
                    const ull* pd = (const ull*)(sP + l * 20);
#pragma unroll
                    for (int hh = 0; hh < Hn; hh++) {
                        w0[hh] = fma2(pd[hh], ev.x, w0[hh]);
                        w1[hh] = fma2(pd[hh], ev.y, w1[hh]);
                    }
                }
            }
            __syncthreads();
            if (tt + 2 < ntiles)
                load_tile_async(embp + (size_t)(tt + 2) * TL * Dn, smb + cur * (TL * STR * 4), t);
        }
    }
    __syncthreads();

    // cross-warp reduce + write partial
    {
        int dq = t & 31;
        ulonglong2* Wst = (ulonglong2*)sm;
#pragma unroll
        for (int i = 0; i < Hn; i++) {
            ulonglong2 v; v.x = w0[i]; v.y = w1[i];
            Wst[(wrp * 8 + i) * 32 + dq] = v;
        }
    }
    __syncthreads();
    {
        int h2 = t >> 5, dq2 = t & 31;
        const float4* Wstf = (const float4*)sm;
        float4 acc = make_float4(0.f, 0.f, 0.f, 0.f);
#pragma unroll
        for (int g = 0; g < 8; g++) {
            float4 v = Wstf[(g * 8 + h2) * 32 + dq2];
            acc.x += v.x; acc.y += v.y; acc.z += v.z; acc.w += v.w;
        }
        float* gp = g_part + (size_t)blk * 1040;
        *(float4*)(gp + 16 + h2 * Dn + 4 * dq2) = acc;
        if (t < 8) { gp[t] = sM[t]; gp[8 + t] = sZ[t]; }
    }
}

// ---------------- Kernel 4: combine partials + epilogue (Gv folded on the fly) ----------------
__global__ void combine(const float* __restrict__ Wvp, const float* __restrict__ Wv,
                        const float* __restrict__ Wo, float* __restrict__ out) {
    __shared__ float cc[SPLIT * Hn];
    __shared__ float wfs[Hn][Dn];
    __shared__ float vmid[Hn * Dn];
    __shared__ float sCtx[Hn * DKn];
    int b = blockIdx.x, a = b & 7, t = threadIdx.x;  // 128 threads
    const float* P0 = g_part + (size_t)(b * SPLIT) * 1040;
    const float* P1 = P0 + 1040;
    const float* P2 = P1 + 1040;
    const float* P3 = P2 + 1040;

    if (t < 8) {
        float m0 = P0[t], m1 = P1[t], m2 = P2[t], m3 = P3[t];
        float mm = fmaxf(fmaxf(m0, m1), fmaxf(m2, m3));
        float a0 = ex2(m0 - mm), a1 = ex2(m1 - mm), a2 = ex2(m2 - mm), a3 = ex2(m3 - mm);
        float inv = 1.f / (P0[8 + t] * a0 + P1[8 + t] * a1 + P2[8 + t] * a2 + P3[8 + t] * a3);
        cc[t] = a0 * inv; cc[8 + t] = a1 * inv; cc[16 + t] = a2 * inv; cc[24 + t] = a3 * inv;
    }
    __syncthreads();

#pragma unroll
    for (int h = 0; h < Hn; h++) {
        int off = 16 + h * Dn + t;
        wfs[h][t] = P0[off] * cc[h] + P1[off] * cc[8 + h] + P2[off] * cc[16 + h] + P3[off] * cc[24 + h];
    }
    __syncthreads();

    {   // vmid[h][t] = wfs[h] @ Wvp + a*Wvp[128]
        float acc[Hn];
        float bias = (float)a * Wvp[Dn * Dn + t];
#pragma unroll
        for (int h = 0; h < Hn; h++) acc[h] = bias;
#pragma unroll 4
        for (int i = 0; i < Dn; i++) {
            float wv = Wvp[i * Dn + t];
#pragma unroll
            for (int h = 0; h < Hn; h++) acc[h] += wfs[h][i] * wv;
        }
#pragma unroll
        for (int h = 0; h < Hn; h++) vmid[h * Dn + t] = acc[h];
    }
    __syncthreads();

    {   // ctx[h][k] = vmid[h] @ Wv[h]
        int h = t >> 4, k = t & 15;
        const float* wvr = Wv + h * Dn * DKn + k;
        const float* vm = vmid + h * Dn;
        float acc = 0.f;
#pragma unroll 4
        for (int d = 0; d < Dn; d++) acc += vm[d] * wvr[d * DKn];
        sCtx[t] = acc;
    }
    __syncthreads();

    {   // out = ctx @ Wo
        float acc = 0.f;
#pragma unroll 4
        for (int j = 0; j < Hn * DKn; j++) acc += sCtx[j] * Wo[j * Dn + t];
        out[(size_t)b * Dn + t] = acc;
    }
}

// ---------------------------------------------------------------------------
extern "C" void kernel_launch(void* const* d_in, const int* in_sizes, int n_in,
                              void* d_out, int out_size) {
    const float* gc      = (const float*)d_in[0];
    const float* depot   = (const float*)d_in[1];
    const float* tbd     = (const float*)d_in[2];
    const float* loadv   = (const float*)d_in[3];
    const float* emb     = (const float*)d_in[4];
    const int*   lens    = (const int*)  d_in[5];
    const float* Wq_proj = (const float*)d_in[6];
    const float* Wk_proj = (const float*)d_in[7];
    const float* Wv_proj = (const float*)d_in[8];
    const float* Wq      = (const float*)d_in[9];
    const float* Wk      = (const float*)d_in[10];
    const float* Wv      = (const float*)d_in[11];
    const float* Wo      = (const float*)d_in[12];
    float* out = (float*)d_out;

    prep_base<<<3 * En, 128>>>(gc, depot, tbd, Wq_proj);
    prep_Rk<<<EA, 128>>>(loadv, Wq_proj, Wq, Wk, Wk_proj);

    cudaFuncSetAttribute(decoder_main, cudaFuncAttributeMaxDynamicSharedMemorySize, SMEM_BYTES);
    decoder_main<<<EA * SPLIT, 256, SMEM_BYTES>>>(emb, lens);

    combine<<<EA, 128>>>(Wv_proj, Wv, Wo, out);
}

// round 11
// speedup vs baseline: 1.2648x; 1.0200x over previous
#include <cuda_runtime.h>
#include <cstdint>

#define En 64
#define An 8
#define Ln 2048
#define Dn 128
#define Hn 8
#define DKn 16
#define EA 512
#define SPLIT 4
#define RPS 512
#define TL 64
#define STR 132

typedef unsigned long long ull;

__device__ __forceinline__ ull fma2(ull a, ull b, ull c) {
    ull d; asm("fma.rn.f32x2 %0, %1, %2, %3;" : "=l"(d) : "l"(a), "l"(b), "l"(c)); return d;
}
__device__ __forceinline__ ull mul2(ull a, ull b) {
    ull d; asm("mul.rn.f32x2 %0, %1, %2;" : "=l"(d) : "l"(a), "l"(b)); return d;
}
__device__ __forceinline__ float2 unpack2(ull v) {
    float2 r; asm("mov.b64 {%0,%1}, %2;" : "=f"(r.x), "=f"(r.y) : "l"(v)); return r;
}
__device__ __forceinline__ float ex2(float x) {
    float y; asm("ex2.approx.ftz.f32 %0, %1;" : "=f"(y) : "f"(x)); return y;
}

__device__ __align__(16) float g_Rk[EA * Hn * Dn];
__device__ __align__(16) float g_part[EA * SPLIT * 1040];  // m[8],Z[8],w[8][128]
__device__ int g_cnt[EA];

// ---------------- Kernel 1: full query pipeline -> Rk (coalesced Wkp access) ----------------
__global__ void prep(const float* __restrict__ gc, const float* __restrict__ dep,
                     const float* __restrict__ tbd, const float* __restrict__ loadv,
                     const float* __restrict__ Wqp, const float* __restrict__ Wq,
                     const float* __restrict__ Wk, const float* __restrict__ Wkp) {
    __shared__ float qsm[Dn];
    __shared__ float qhs[Hn * DKn];
    __shared__ float ut[Hn * 132];
    int b = blockIdx.x, e = b >> 3, a = b & 7, t = threadIdx.x;  // 256 threads

    if (t < Dn) {  // q[t]
        float acc = loadv[e * An + a] * Wqp[384 * Dn + t] + (float)a * Wqp[385 * Dn + t];
        const float* s0 = gc + e * Dn; const float* s1 = dep + e * Dn; const float* s2 = tbd + e * Dn;
#pragma unroll 4
        for (int i = 0; i < Dn; i++) {
            acc += s0[i] * Wqp[i * Dn + t];
            acc += s1[i] * Wqp[(Dn + i) * Dn + t];
            acc += s2[i] * Wqp[(2 * Dn + i) * Dn + t];
        }
        qsm[t] = acc;
    }
    __syncthreads();
    if (t < Dn) {  // qh[h][k]
        int h = t >> 4, k = t & 15;
        float acc = 0.f;
#pragma unroll 4
        for (int d = 0; d < Dn; d++) acc += qsm[d] * Wq[(h * Dn + d) * DKn + k];
        qhs[t] = acc;
    }
    __syncthreads();
    if (t < Dn) {  // u[h][d=t], SC folded
        const float SC = 0.25f * 1.4426950408889634f;
#pragma unroll
        for (int h = 0; h < Hn; h++) {
            const float* wkr = Wk + (h * Dn + t) * DKn;
            const float* qh = qhs + h * DKn;
            float acc = 0.f;
#pragma unroll
            for (int k = 0; k < DKn; k++) acc += qh[k] * wkr[k];
            ut[h * 132 + t] = SC * acc;
        }
    }
    __syncthreads();
    {  // Rk[h][i] = sum_d Wkp[i][d]*u[h][d]; thread (i=t>>1, half=t&1) does 64 d's
        int i = t >> 1, half = t & 1;
        const float* wrow = Wkp + i * Dn + 64 * half;
        float acc[Hn];
#pragma unroll
        for (int h = 0; h < Hn; h++) acc[h] = 0.f;
#pragma unroll
        for (int p = 0; p < 4; p++) {
            float4 v0 = *(const float4*)(wrow + 16 * p);
            float4 v1 = *(const float4*)(wrow + 16 * p + 4);
            float4 v2 = *(const float4*)(wrow + 16 * p + 8);
            float4 v3 = *(const float4*)(wrow + 16 * p + 12);
#pragma unroll
            for (int h = 0; h < Hn; h++) {
                const float* u = ut + h * 132 + 64 * half + 16 * p;
                acc[h] += v0.x*u[0] + v0.y*u[1] + v0.z*u[2] + v0.w*u[3]
                        + v1.x*u[4] + v1.y*u[5] + v1.z*u[6] + v1.w*u[7]
                        + v2.x*u[8] + v2.y*u[9] + v2.z*u[10] + v2.w*u[11]
                        + v3.x*u[12] + v3.y*u[13] + v3.z*u[14] + v3.w*u[15];
            }
        }
#pragma unroll
        for (int h = 0; h < Hn; h++) acc[h] += __shfl_xor_sync(0xffffffffu, acc[h], 1);
        if (!half)
#pragma unroll
            for (int h = 0; h < Hn; h++) g_Rk[((size_t)b * Hn + h) * Dn + i] = acc[h];
    }
}

// ---------------- Kernel 2: main + inlined combine. CTA per (e,a,split). 256 thr ----------------
#define SM_SS 16896
#define SM_SP 17472
#define SM_M  18752
#define SM_Z  18760
#define SM_F  18768
#define SMEM_BYTES (18784 * 4)

__device__ __forceinline__ void load_tile_async(const float* src, uint32_t dbase, int t) {
#pragma unroll
    for (int j = 0; j < 8; j++) {
        int c = t + 256 * j, l = c >> 5, s = c & 31;
        uint32_t dst = dbase + (uint32_t)(l * (STR * 4) + s * 16);
        asm volatile("cp.async.cg.shared.global [%0], [%1], 16;\n"
                     :: "r"(dst), "l"(src + l * Dn + s * 4) : "memory");
    }
    asm volatile("cp.async.commit_group;\n" ::: "memory");
}

__global__ __launch_bounds__(256, 2)
void decoder_main(const float* __restrict__ emb, const int* __restrict__ lens,
                  const float* __restrict__ Wvp, const float* __restrict__ Wv,
                  const float* __restrict__ Wo, float* __restrict__ out) {
    extern __shared__ float sm[];
    __shared__ int sflag;
    float*  sS  = sm + SM_SS;
    float*  sP  = sm + SM_SP;
    float*  sM  = sm + SM_M;
    float*  sZ  = sm + SM_Z;
    float2* sF2 = (float2*)(sm + SM_F);

    int blk = blockIdx.x, b = blk >> 2, sp = blk & 3, t = threadIdx.x;
    int len = lens[b];
    int cnt = min(len - sp * RPS, RPS);
    int ntiles = (cnt > 0) ? ((cnt + TL - 1) >> 6) : 0;
    const float* embp = emb + (size_t)b * (Ln * Dn) + (size_t)sp * RPS * Dn;

    int h = t & 7, q = (t >> 3) & 3, wrp = t >> 5;

    ull rk[16];
    {
        const float* rbase = g_Rk + ((size_t)b * Hn + h) * Dn + 4 * q;
#pragma unroll
        for (int j = 0; j < 8; j++) {
            ulonglong2 v = *(const ulonglong2*)(rbase + 16 * j);
            rk[2 * j] = v.x; rk[2 * j + 1] = v.y;
        }
    }
    if (t < 8) { sM[t] = -1e30f; sZ[t] = 0.f; }

    ull w0[Hn], w1[Hn];
#pragma unroll
    for (int i = 0; i < Hn; i++) { w0[i] = 0ull; w1[i] = 0ull; }

    uint32_t smb = (uint32_t)__cvta_generic_to_shared(sm);

    if (ntiles > 0) {
        load_tile_async(embp, smb, t);
        if (ntiles > 1) load_tile_async(embp + TL * Dn, smb + TL * STR * 4, t);

        for (int tt = 0; tt < ntiles; tt++) {
            int cur = tt & 1;
            if (tt + 1 < ntiles) asm volatile("cp.async.wait_group 1;\n" ::: "memory");
            else                 asm volatile("cp.async.wait_group 0;\n" ::: "memory");
            __syncthreads();
            const float* tb = sm + cur * (TL * STR);

            // score: warp wrp -> rows wrp*8..+7; lane (h,q)
#pragma unroll
            for (int i = 0; i < 8; i++) {
                int row = wrp * 8 + i;
                const ulonglong2* rp = (const ulonglong2*)(tb + row * STR + 4 * q);
                ull a0 = 0ull, a1 = 0ull;
#pragma unroll
                for (int j = 0; j < 8; j++) {
                    ulonglong2 ev = rp[4 * j];
                    a0 = fma2(ev.x, rk[2 * j], a0);
                    a1 = fma2(ev.y, rk[2 * j + 1], a1);
                }
                float2 fa = unpack2(a0), fb = unpack2(a1);
                float s = (fa.x + fa.y) + (fb.x + fb.y);
                s += __shfl_xor_sync(0xffffffffu, s, 8);
                s += __shfl_xor_sync(0xffffffffu, s, 16);
                if (tt * TL + row >= cnt) s = -1e30f;
                if (q == 0) sS[row * 9 + h] = s;
            }
            __syncthreads();

            // online softmax: warp wrp = head
            {
                int j = t & 31;
                float v0 = sS[j * 9 + wrp], v1 = sS[(j + 32) * 9 + wrp];
                float tm = fmaxf(v0, v1);
#pragma unroll
                for (int o = 16; o; o >>= 1) tm = fmaxf(tm, __shfl_xor_sync(0xffffffffu, tm, o));
                float mo = sM[wrp], mn = fmaxf(mo, tm);
                float p0 = ex2(v0 - mn), p1 = ex2(v1 - mn);
                float ps = p0 + p1;
#pragma unroll
                for (int o = 16; o; o >>= 1) ps += __shfl_xor_sync(0xffffffffu, ps, o);
                if (j == 0) {
                    float fh = ex2(mo - mn);
                    sF2[wrp] = make_float2(fh, fh);
                    sM[wrp] = mn;
                    sZ[wrp] = sZ[wrp] * fh + ps;
                }
                *(float2*)(sP + j * 20 + 2 * wrp)        = make_float2(p0, p0);
                *(float2*)(sP + (j + 32) * 20 + 2 * wrp) = make_float2(p1, p1);
            }
            __syncthreads();

            // accumulate: warp wrp -> rows wrp*8..+7; lane dq -> floats 4dq..+3
            {
                int dq = t & 31;
#pragma unroll
                for (int i = 0; i < Hn; i++) {
                    ull f2v = ((const ull*)sF2)[i];
                    w0[i] = mul2(w0[i], f2v);
                    w1[i] = mul2(w1[i], f2v);
                }
#pragma unroll
                for (int i = 0; i < 8; i++) {
                    int l = wrp * 8 + i;
                    ulonglong2 ev = *(const ulonglong2*)(tb + l * STR + 4 * dq);
                    const ull* pd = (const ull*)(sP + l * 20);
#pragma unroll
                    for (int hh = 0; hh < Hn; hh++) {
                        w0[hh] = fma2(pd[hh], ev.x, w0[hh]);
                        w1[hh] = fma2(pd[hh], ev.y, w1[hh]);
                    }
                }
            }
            __syncthreads();
            if (tt + 2 < ntiles)
                load_tile_async(embp + (size_t)(tt + 2) * TL * Dn, smb + cur * (TL * STR * 4), t);
        }
    }
    __syncthreads();

    // cross-warp reduce + write partial
    {
        int dq = t & 31;
        ulonglong2* Wst = (ulonglong2*)sm;
#pragma unroll
        for (int i = 0; i < Hn; i++) {
            ulonglong2 v; v.x = w0[i]; v.y = w1[i];
            Wst[(wrp * 8 + i) * 32 + dq] = v;
        }
    }
    __syncthreads();
    {
        int h2 = t >> 5, dq2 = t & 31;
        const float4* Wstf = (const float4*)sm;
        float4 acc = make_float4(0.f, 0.f, 0.f, 0.f);
#pragma unroll
        for (int g = 0; g < 8; g++) {
            float4 v = Wstf[(g * 8 + h2) * 32 + dq2];
            acc.x += v.x; acc.y += v.y; acc.z += v.z; acc.w += v.w;
        }
        float* gp = g_part + (size_t)blk * 1040;
        *(float4*)(gp + 16 + h2 * Dn + 4 * dq2) = acc;
        if (t < 8) { gp[t] = sM[t]; gp[8 + t] = sZ[t]; }
    }
    __syncthreads();

    // ---- last-arriver does the combine + epilogue for this (e,a) pair ----
    __threadfence();
    if (t == 0) {
        int r = atomicAdd(&g_cnt[b], 1);
        sflag = (r == SPLIT - 1);
        if (r == SPLIT - 1) g_cnt[b] = 0;
    }
    __syncthreads();
    if (!sflag) return;
    __threadfence();

    int a = b & 7;
    float* cc   = sm;          // [4][8]
    float* wfs  = sm + 32;     // [8][128]
    float* vmid = sm + 32 + Hn * Dn;
    float* sCtx = vmid + Hn * Dn;
    const float* P0 = g_part + (size_t)(b * SPLIT) * 1040;
    const float* P1 = P0 + 1040;
    const float* P2 = P1 + 1040;
    const float* P3 = P2 + 1040;

    if (t < 8) {
        float m0 = P0[t], m1 = P1[t], m2 = P2[t], m3 = P3[t];
        float mm = fmaxf(fmaxf(m0, m1), fmaxf(m2, m3));
        float a0 = ex2(m0 - mm), a1 = ex2(m1 - mm), a2 = ex2(m2 - mm), a3 = ex2(m3 - mm);
        float inv = 1.f / (P0[8 + t] * a0 + P1[8 + t] * a1 + P2[8 + t] * a2 + P3[8 + t] * a3);
        cc[t] = a0 * inv; cc[8 + t] = a1 * inv; cc[16 + t] = a2 * inv; cc[24 + t] = a3 * inv;
    }
    __syncthreads();
    if (t < 128) {
#pragma unroll
        for (int hh = 0; hh < Hn; hh++) {
            int off = 16 + hh * Dn + t;
            wfs[hh * Dn + t] = P0[off] * cc[hh] + P1[off] * cc[8 + hh]
                             + P2[off] * cc[16 + hh] + P3[off] * cc[24 + hh];
        }
    }
    __syncthreads();
    if (t < 128) {  // vmid[h][t] = wfs[h] @ Wvp + a*Wvp[128]
        float acc[Hn];
        float bias = (float)a * Wvp[Dn * Dn + t];
#pragma unroll
        for (int hh = 0; hh < Hn; hh++) acc[hh] = bias;
#pragma unroll 4
        for (int i = 0; i < Dn; i++) {
            float wv = Wvp[i * Dn + t];
#pragma unroll
            for (int hh = 0; hh < Hn; hh++) acc[hh] += wfs[hh * Dn + i] * wv;
        }
#pragma unroll
        for (int hh = 0; hh < Hn; hh++) vmid[hh * Dn + t] = acc[hh];
    }
    __syncthreads();
    if (t < 128) {  // ctx[h][k]
        int hh = t >> 4, k = t & 15;
        const float* wvr = Wv + hh * Dn * DKn + k;
        const float* vm = vmid + hh * Dn;
        float acc = 0.f;
#pragma unroll 4
        for (int d = 0; d < Dn; d++) acc += vm[d] * wvr[d * DKn];
        sCtx[t] = acc;
    }
    __syncthreads();
    if (t < 128) {  // out = ctx @ Wo
        float acc = 0.f;
#pragma unroll 4
        for (int j = 0; j < Hn * DKn; j++) acc += sCtx[j] * Wo[j * Dn + t];
        out[(size_t)b * Dn + t] = acc;
    }
}

// ---------------------------------------------------------------------------
extern "C" void kernel_launch(void* const* d_in, const int* in_sizes, int n_in,
                              void* d_out, int out_size) {
    const float* gc      = (const float*)d_in[0];
    const float* depot   = (const float*)d_in[1];
    const float* tbd     = (const float*)d_in[2];
    const float* loadv   = (const float*)d_in[3];
    const float* emb     = (const float*)d_in[4];
    const int*   lens    = (const int*)  d_in[5];
    const float* Wq_proj = (const float*)d_in[6];
    const float* Wk_proj = (const float*)d_in[7];
    const float* Wv_proj = (const float*)d_in[8];
    const float* Wq      = (const float*)d_in[9];
    const float* Wk      = (const float*)d_in[10];
    const float* Wv      = (const float*)d_in[11];
    const float* Wo      = (const float*)d_in[12];
    float* out = (float*)d_out;

    prep<<<EA, 256>>>(gc, depot, tbd, loadv, Wq_proj, Wq, Wk, Wk_proj);

    cudaFuncSetAttribute(decoder_main, cudaFuncAttributeMaxDynamicSharedMemorySize, SMEM_BYTES);
    decoder_main<<<EA * SPLIT, 256, SMEM_BYTES>>>(emb, lens, Wv_proj, Wv, Wo, out);
}

// round 12
// speedup vs baseline: 1.4556x; 1.1509x over previous
#include <cuda_runtime.h>
#include <cstdint>

#define En 64
#define An 8
#define Ln 2048
#define Dn 128
#define Hn 8
#define DKn 16
#define EA 512
#define SPLIT 4
#define RPS 512
#define TL 64
#define WSTR 132           // padded row stride inside a warp tile (floats)
#define WTILE (2 * 8 * WSTR)   // 2112 floats per warp (two 8-row buffers)

typedef unsigned long long ull;

__device__ __forceinline__ ull fma2(ull a, ull b, ull c) {
    ull d; asm("fma.rn.f32x2 %0, %1, %2, %3;" : "=l"(d) : "l"(a), "l"(b), "l"(c)); return d;
}
__device__ __forceinline__ ull mul2(ull a, ull b) {
    ull d; asm("mul.rn.f32x2 %0, %1, %2;" : "=l"(d) : "l"(a), "l"(b)); return d;
}
__device__ __forceinline__ ull pack2(float x, float y) {
    ull r; asm("mov.b64 %0, {%1,%2};" : "=l"(r) : "f"(x), "f"(y)); return r;
}
__device__ __forceinline__ float2 unpack2(ull v) {
    float2 r; asm("mov.b64 {%0,%1}, %2;" : "=f"(r.x), "=f"(r.y) : "l"(v)); return r;
}
__device__ __forceinline__ float ex2(float x) {
    float y; asm("ex2.approx.ftz.f32 %0, %1;" : "=f"(y) : "f"(x)); return y;
}

__device__ __align__(16) float g_bq[3 * En * Dn];
__device__ __align__(16) float g_Rk[EA * Hn * Dn];
__device__ __align__(16) float g_part[EA * SPLIT * 1040];  // m[8],Z[8],w[8][128]
__device__ int g_cnt[EA];

// ---------------- Kernel 0: A-independent base query (once per e) ----------------
__global__ void prep_base(const float* __restrict__ gc, const float* __restrict__ dep,
                          const float* __restrict__ tbd, const float* __restrict__ Wqp) {
    int e = blockIdx.x, seg = threadIdx.x >> 7, t = threadIdx.x & 127;  // 384 threads
    const float* src = ((seg == 0) ? gc : (seg == 1) ? dep : tbd) + e * Dn;
    const float* wp = Wqp + seg * Dn * Dn + t;
    float a0 = 0.f, a1 = 0.f, a2 = 0.f, a3 = 0.f;
#pragma unroll 8
    for (int i = 0; i < Dn; i += 4) {
        a0 += src[i] * wp[i * Dn];
        a1 += src[i + 1] * wp[(i + 1) * Dn];
        a2 += src[i + 2] * wp[(i + 2) * Dn];
        a3 += src[i + 3] * wp[(i + 3) * Dn];
    }
    g_bq[(seg * En + e) * Dn + t] = (a0 + a1) + (a2 + a3);
}

// ---------------- Kernel 1: per-(e,a) -> Rk (scale+log2e folded; agent-id K col drops) --------
__global__ void prep_Rk(const float* __restrict__ loadv, const float* __restrict__ Wqp,
                        const float* __restrict__ Wq, const float* __restrict__ Wk,
                        const float* __restrict__ Wkp) {
    __shared__ float qsm[Dn];
    __shared__ float qhs[Hn * DKn];
    __shared__ float ut[Hn * 132];
    int b = blockIdx.x, e = b >> 3, a = b & 7, t = threadIdx.x;  // 256 threads

    if (t < Dn) {
        qsm[t] = g_bq[e * Dn + t] + g_bq[(En + e) * Dn + t] + g_bq[(2 * En + e) * Dn + t]
               + loadv[e * An + a] * Wqp[384 * Dn + t] + (float)a * Wqp[385 * Dn + t];
    }
    __syncthreads();
    if (t < Dn) {  // qh[h][k]
        int h = t >> 4, k = t & 15;
        float acc = 0.f;
#pragma unroll 4
        for (int d = 0; d < Dn; d++) acc += qsm[d] * Wq[(h * Dn + d) * DKn + k];
        qhs[t] = acc;
    }
    __syncthreads();
    if (t < Dn) {  // u[h][d=t], SC folded
        const float SC = 0.25f * 1.4426950408889634f;
#pragma unroll
        for (int h = 0; h < Hn; h++) {
            const float* wkr = Wk + (h * Dn + t) * DKn;
            const float* qh = qhs + h * DKn;
            float acc = 0.f;
#pragma unroll
            for (int k = 0; k < DKn; k++) acc += qh[k] * wkr[k];
            ut[h * 132 + t] = SC * acc;
        }
    }
    __syncthreads();
    {  // Rk[h][i] = sum_d Wkp[i][d]*u[h][d]; thread (i=t>>1, half=t&1)
        int i = t >> 1, half = t & 1;
        const float* wrow = Wkp + i * Dn + 64 * half;
        float acc[Hn];
#pragma unroll
        for (int h = 0; h < Hn; h++) acc[h] = 0.f;
#pragma unroll
        for (int p = 0; p < 4; p++) {
            float4 v0 = *(const float4*)(wrow + 16 * p);
            float4 v1 = *(const float4*)(wrow + 16 * p + 4);
            float4 v2 = *(const float4*)(wrow + 16 * p + 8);
            float4 v3 = *(const float4*)(wrow + 16 * p + 12);
#pragma unroll
            for (int h = 0; h < Hn; h++) {
                const float* u = ut + h * 132 + 64 * half + 16 * p;
                acc[h] += v0.x*u[0] + v0.y*u[1] + v0.z*u[2] + v0.w*u[3]
                        + v1.x*u[4] + v1.y*u[5] + v1.z*u[6] + v1.w*u[7]
                        + v2.x*u[8] + v2.y*u[9] + v2.z*u[10] + v2.w*u[11]
                        + v3.x*u[12] + v3.y*u[13] + v3.z*u[14] + v3.w*u[15];
            }
        }
#pragma unroll
        for (int h = 0; h < Hn; h++) acc[h] += __shfl_xor_sync(0xffffffffu, acc[h], 1);
        if (!half)
#pragma unroll
            for (int h = 0; h < Hn; h++) g_Rk[((size_t)b * Hn + h) * Dn + i] = acc[h];
    }
}

// ---------------- Kernel 2: main, barrier-free per-warp streaming ----------------
// smem floats: [0,16896) 8 warp-tiles (2 bufs x 8 rows x 132) | sPd [8][128] @16896
//              sMZ [8][16] @17920 | epilogue aliases sm[0]
#define SM_PD 16896
#define SM_MZ 17920
#define SMEM_BYTES ((SM_MZ + 128) * 4)

__global__ __launch_bounds__(256, 2)
void decoder_main(const float* __restrict__ emb, const int* __restrict__ lens,
                  const float* __restrict__ Wvp, const float* __restrict__ Wv,
                  const float* __restrict__ Wo, float* __restrict__ out) {
    extern __shared__ float sm[];
    __shared__ int sflag;

    int blk = blockIdx.x, b = blk >> 2, sp = blk & 3, t = threadIdx.x;
    int wrp = t >> 5, lane = t & 31, h = lane & 7, q = lane >> 3;
    int len = lens[b];
    int cnt = min(len - sp * RPS, RPS);
    int ntiles = (cnt > 0) ? ((cnt + TL - 1) >> 6) : 0;
    const float* embp = emb + (size_t)b * (Ln * Dn) + (size_t)sp * RPS * Dn;

    float* wbuf = sm + wrp * WTILE;
    float* sPd  = sm + SM_PD + wrp * 128;
    float* sMZ  = sm + SM_MZ;
    uint32_t wdst = (uint32_t)__cvta_generic_to_shared(wbuf) + (uint32_t)lane * 16;

    // Rk registers: lane (h,q) holds floats {16j+4q..+3}
    ull rk[16];
    {
        const float* rbase = g_Rk + ((size_t)b * Hn + h) * Dn + 4 * q;
#pragma unroll
        for (int j = 0; j < 8; j++) {
            ulonglong2 v = *(const ulonglong2*)(rbase + 16 * j);
            rk[2 * j] = v.x; rk[2 * j + 1] = v.y;
        }
    }

    float m = -30000.f, Z = 0.f;
    ull w0[Hn], w1[Hn];
#pragma unroll
    for (int i = 0; i < Hn; i++) { w0[i] = 0ull; w1[i] = 0ull; }

#define LD_STRIPE(tt, bufk)                                                              \
    do {                                                                                  \
        const float* _s = embp + (size_t)((tt) * TL + wrp * 8) * Dn + lane * 4;           \
        uint32_t _d = wdst + (uint32_t)(bufk) * (8 * WSTR * 4);                           \
        _Pragma("unroll")                                                                 \
        for (int _i = 0; _i < 8; _i++)                                                    \
            asm volatile("cp.async.cg.shared.global [%0], [%1], 16;\n"                    \
                         :: "r"(_d + _i * (WSTR * 4)), "l"(_s + _i * Dn) : "memory");     \
        asm volatile("cp.async.commit_group;\n" ::: "memory");                            \
    } while (0)

    if (ntiles > 0) {
        LD_STRIPE(0, 0);
        if (ntiles > 1) LD_STRIPE(1, 1);

        for (int tt = 0; tt < ntiles; tt++) {
            if (tt + 1 < ntiles) asm volatile("cp.async.wait_group 1;\n" ::: "memory");
            else                 asm volatile("cp.async.wait_group 0;\n" ::: "memory");
            __syncwarp();
            const float* tb = wbuf + (tt & 1) * (8 * WSTR);
            int base = tt * TL + wrp * 8;

            // score: 8 rows, lane (h,q) covers d-chunk q; full dot after 2 shfls
            float s[8];
#pragma unroll
            for (int i = 0; i < 8; i++) {
                const ulonglong2* rp = (const ulonglong2*)(tb + i * WSTR + 4 * q);
                ull a0 = 0ull, a1 = 0ull;
#pragma unroll
                for (int j = 0; j < 8; j++) {
                    ulonglong2 ev = rp[4 * j];
                    a0 = fma2(ev.x, rk[2 * j], a0);
                    a1 = fma2(ev.y, rk[2 * j + 1], a1);
                }
                float2 fa = unpack2(a0), fb = unpack2(a1);
                float sv = (fa.x + fa.y) + (fb.x + fb.y);
                sv += __shfl_xor_sync(0xffffffffu, sv, 8);
                sv += __shfl_xor_sync(0xffffffffu, sv, 16);
                s[i] = (base + i < cnt) ? sv : -1e30f;
            }

            // per-warp online softmax (per-lane state for head h, duplicated over q)
            float tm = s[0];
#pragma unroll
            for (int i = 1; i < 8; i++) tm = fmaxf(tm, s[i]);
            float mn = fmaxf(m, tm);
            float f = ex2(m - mn);
            m = mn;
            float p[8], zs = 0.f;
#pragma unroll
            for (int i = 0; i < 8; i++) {
                p[i] = (s[i] > -1e29f) ? ex2(s[i] - mn) : 0.f;
                zs += p[i];
            }
            Z = Z * f + zs;

            // stash p duplicated: lane (h,q) writes rows q and q+4
            *(float2*)(sPd + q * 16 + 2 * h)       = make_float2(p[q], p[q]);
            *(float2*)(sPd + (q + 4) * 16 + 2 * h) = make_float2(p[q + 4], p[q + 4]);
            __syncwarp();

            // rescale accumulators (need f of every head)
#pragma unroll
            for (int hh = 0; hh < Hn; hh++) {
                float fh = __shfl_sync(0xffffffffu, f, hh);
                ull fp = pack2(fh, fh);
                w0[hh] = mul2(w0[hh], fp);
                w1[hh] = mul2(w1[hh], fp);
            }
            // accumulate: lane = dq covers floats 4*lane..+3
#pragma unroll
            for (int i = 0; i < 8; i++) {
                ulonglong2 ev = *(const ulonglong2*)(tb + i * WSTR + 4 * lane);
                const ull* pd = (const ull*)(sPd + i * 16);
#pragma unroll
                for (int hh = 0; hh < Hn; hh++) {
                    w0[hh] = fma2(pd[hh], ev.x, w0[hh]);
                    w1[hh] = fma2(pd[hh], ev.y, w1[hh]);
                }
            }
            __syncwarp();
            if (tt + 2 < ntiles) LD_STRIPE(tt + 2, tt & 1);
        }
    }

    // ---- CTA merge of 8 per-warp partials ----
    if (q == 0) { sMZ[wrp * 16 + h] = m; sMZ[wrp * 16 + 8 + h] = Z; }
    __syncthreads();  // all warps done; tile region reusable
    {
        ulonglong2* Wm = (ulonglong2*)sm;  // [8 warps][8 heads][32 lanes] x 16B = 32KB
#pragma unroll
        for (int hh = 0; hh < Hn; hh++) {
            ulonglong2 v; v.x = w0[hh]; v.y = w1[hh];
            Wm[(wrp * 8 + hh) * 32 + lane] = v;
        }
    }
    __syncthreads();
    {
        int h2 = t >> 5, dq2 = t & 31;
        float mc = sMZ[h2];
#pragma unroll
        for (int wv = 1; wv < 8; wv++) mc = fmaxf(mc, sMZ[wv * 16 + h2]);
        float fw[8], Zc = 0.f;
#pragma unroll
        for (int wv = 0; wv < 8; wv++) {
            fw[wv] = ex2(sMZ[wv * 16 + h2] - mc);
            Zc += sMZ[wv * 16 + 8 + h2] * fw[wv];
        }
        const float4* Wmf = (const float4*)sm;
        float4 acc = make_float4(0.f, 0.f, 0.f, 0.f);
#pragma unroll
        for (int wv = 0; wv < 8; wv++) {
            float4 v = Wmf[(wv * 8 + h2) * 32 + dq2];
            acc.x += fw[wv] * v.x; acc.y += fw[wv] * v.y;
            acc.z += fw[wv] * v.z; acc.w += fw[wv] * v.w;
        }
        float* gp = g_part + (size_t)blk * 1040;
        *(float4*)(gp + 16 + h2 * Dn + 4 * dq2) = acc;
        if (dq2 == 0) { gp[h2] = mc; gp[8 + h2] = Zc; }
    }
    __syncthreads();

    // ---- last-arriver combine + epilogue for this (e,a) ----
    __threadfence();
    if (t == 0) {
        int r = atomicAdd(&g_cnt[b], 1);
        sflag = (r == SPLIT - 1);
        if (r == SPLIT - 1) g_cnt[b] = 0;
    }
    __syncthreads();
    if (!sflag) return;
    __threadfence();

    int a = b & 7;
    float* cc   = sm;                    // [4][8]
    float* wfs  = sm + 32;               // [8][128]
    float* vmid = sm + 32 + Hn * Dn;
    float* sCtx = vmid + Hn * Dn;
    const float* P0 = g_part + (size_t)(b * SPLIT) * 1040;
    const float* P1 = P0 + 1040;
    const float* P2 = P1 + 1040;
    const float* P3 = P2 + 1040;

    if (t < 8) {
        float m0 = P0[t], m1 = P1[t], m2 = P2[t], m3 = P3[t];
        float mm = fmaxf(fmaxf(m0, m1), fmaxf(m2, m3));
        float a0 = ex2(m0 - mm), a1 = ex2(m1 - mm), a2 = ex2(m2 - mm), a3 = ex2(m3 - mm);
        float inv = 1.f / (P0[8 + t] * a0 + P1[8 + t] * a1 + P2[8 + t] * a2 + P3[8 + t] * a3);
        cc[t] = a0 * inv; cc[8 + t] = a1 * inv; cc[16 + t] = a2 * inv; cc[24 + t] = a3 * inv;
    }
    __syncthreads();
    if (t < 128) {
#pragma unroll
        for (int hh = 0; hh < Hn; hh++) {
            int off = 16 + hh * Dn + t;
            wfs[hh * Dn + t] = P0[off] * cc[hh] + P1[off] * cc[8 + hh]
                             + P2[off] * cc[16 + hh] + P3[off] * cc[24 + hh];
        }
    }
    __syncthreads();
    if (t < 128) {  // vmid[h][t] = wfs[h] @ Wvp + a*Wvp[128]
        float acc[Hn];
        float bias = (float)a * Wvp[Dn * Dn + t];
#pragma unroll
        for (int hh = 0; hh < Hn; hh++) acc[hh] = bias;
#pragma unroll 4
        for (int i = 0; i < Dn; i++) {
            float wv = Wvp[i * Dn + t];
#pragma unroll
            for (int hh = 0; hh < Hn; hh++) acc[hh] += wfs[hh * Dn + i] * wv;
        }
#pragma unroll
        for (int hh = 0; hh < Hn; hh++) vmid[hh * Dn + t] = acc[hh];
    }
    __syncthreads();
    if (t < 128) {  // ctx[h][k]
        int hh = t >> 4, k = t & 15;
        const float* wvr = Wv + hh * Dn * DKn + k;
        const float* vm = vmid + hh * Dn;
        float acc = 0.f;
#pragma unroll 4
        for (int d = 0; d < Dn; d++) acc += vm[d] * wvr[d * DKn];
        sCtx[t] = acc;
    }
    __syncthreads();
    if (t < 128) {  // out = ctx @ Wo
        float acc = 0.f;
#pragma unroll 4
        for (int j = 0; j < Hn * DKn; j++) acc += sCtx[j] * Wo[j * Dn + t];
        out[(size_t)b * Dn + t] = acc;
    }
}

// ---------------------------------------------------------------------------
extern "C" void kernel_launch(void* const* d_in, const int* in_sizes, int n_in,
                              void* d_out, int out_size) {
    const float* gc      = (const float*)d_in[0];
    const float* depot   = (const float*)d_in[1];
    const float* tbd     = (const float*)d_in[2];
    const float* loadv   = (const float*)d_in[3];
    const float* emb     = (const float*)d_in[4];
    const int*   lens    = (const int*)  d_in[5];
    const float* Wq_proj = (const float*)d_in[6];
    const float* Wk_proj = (const float*)d_in[7];
    const float* Wv_proj = (const float*)d_in[8];
    const float* Wq      = (const float*)d_in[9];
    const float* Wk      = (const float*)d_in[10];
    const float* Wv      = (const float*)d_in[11];
    const float* Wo      = (const float*)d_in[12];
    float* out = (float*)d_out;

    prep_base<<<En, 384>>>(gc, depot, tbd, Wq_proj);
    prep_Rk<<<EA, 256>>>(loadv, Wq_proj, Wq, Wk, Wk_proj);

    cudaFuncSetAttribute(decoder_main, cudaFuncAttributeMaxDynamicSharedMemorySize, SMEM_BYTES);
    decoder_main<<<EA * SPLIT, 256, SMEM_BYTES>>>(emb, lens, Wv_proj, Wv, Wo, out);
}